// round 16
// baseline (speedup 1.0000x reference)
#include <cuda_runtime.h>

#define FULLMASK 0xFFFFFFFFu

// Sum of squared differences of two 8-float (2x float4) chunks.
__device__ __forceinline__ float sd8(const float4& a0, const float4& a1,
                                     const float4& b0, const float4& b1) {
    float t, s;
    t = a0.x - b0.x; s = t * t;
    t = a0.y - b0.y; s = fmaf(t, t, s);
    t = a0.z - b0.z; s = fmaf(t, t, s);
    t = a0.w - b0.w; s = fmaf(t, t, s);
    t = a1.x - b1.x; s = fmaf(t, t, s);
    t = a1.y - b1.y; s = fmaf(t, t, s);
    t = a1.z - b1.z; s = fmaf(t, t, s);
    t = a1.w - b1.w; s = fmaf(t, t, s);
    return s;
}

// soft_rank with KL regularization, strength 2.0, n = 4 (register-resident).
__device__ __forceinline__ void softrank4(const float v[4], float out[4]) {
    float th[4];
    int pi[4];
#pragma unroll
    for (int m = 0; m < 4; m++) { th[m] = v[m] * 0.5f; pi[m] = m; }

    // descending sort network on 4 elems: (0,1)(2,3)(0,2)(1,3)(1,2)
#define CSWAP(a, b)                                     \
    do {                                                \
        if (th[a] < th[b]) {                            \
            float tf = th[a]; th[a] = th[b]; th[b] = tf;\
            int ti = pi[a]; pi[a] = pi[b]; pi[b] = ti;  \
        }                                               \
    } while (0)
    CSWAP(0, 1); CSWAP(2, 3); CSWAP(0, 2); CSWAP(1, 3); CSWAP(1, 2);
#undef CSWAP

    const float lcw00 = 1.3862943611198906f;  // log 4
    const float lcw01 = 1.9459101090932196f;  // log 7
    const float lcw02 = 2.1972245773362196f;  // log 9
    const float lcw03 = 2.302585092994046f;   // log 10
    const float lcw11 = 1.0986122886681098f;  // log 3
    const float lcw12 = 1.6094379124341003f;  // log 5
    const float lcw13 = 1.791759469228055f;   // log 6
    const float lcw22 = 0.6931471805599453f;  // log 2
    const float lcw23 = 1.0986122886681098f;  // log 3
    const float lcw33 = 0.0f;                 // log 1

    // B[i][j] = LSE(th[i..j]) - log(cw[i][j]); th descending so th[i] is seg max.
    float B[4][4];
    {
        float run;
        run = 1.0f;                       B[0][0] = th[0] - lcw00;
        run += __expf(th[1] - th[0]);     B[0][1] = th[0] + __logf(run) - lcw01;
        run += __expf(th[2] - th[0]);     B[0][2] = th[0] + __logf(run) - lcw02;
        run += __expf(th[3] - th[0]);     B[0][3] = th[0] + __logf(run) - lcw03;
        run = 1.0f;                       B[1][1] = th[1] - lcw11;
        run += __expf(th[2] - th[1]);     B[1][2] = th[1] + __logf(run) - lcw12;
        run += __expf(th[3] - th[1]);     B[1][3] = th[1] + __logf(run) - lcw13;
        run = 1.0f;                       B[2][2] = th[2] - lcw22;
        run += __expf(th[3] - th[2]);     B[2][3] = th[2] + __logf(run) - lcw23;
        B[3][3] = th[3] - lcw33;
    }

    // dual[k] = min_{i<=k} max_{j>=k} B[i][j]
    float dual[4];
    {
        float T0_3 = B[0][3], T0_2 = fmaxf(B[0][2], T0_3),
              T0_1 = fmaxf(B[0][1], T0_2), T0_0 = fmaxf(B[0][0], T0_1);
        float T1_3 = B[1][3], T1_2 = fmaxf(B[1][2], T1_3),
              T1_1 = fmaxf(B[1][1], T1_2);
        float T2_3 = B[2][3], T2_2 = fmaxf(B[2][2], T2_3);
        float T3_3 = B[3][3];
        dual[0] = T0_0;
        dual[1] = fminf(T0_1, T1_1);
        dual[2] = fminf(fminf(T0_2, T1_2), T2_2);
        dual[3] = fminf(fminf(T0_3, T1_3), fminf(T2_3, T3_3));
    }

#pragma unroll
    for (int k = 0; k < 4; k++) {
        float r = __expf(th[k] - dual[k]);
        out[0] = (pi[k] == 0) ? r : out[0];
        out[1] = (pi[k] == 1) ? r : out[1];
        out[2] = (pi[k] == 2) ? r : out[2];
        out[3] = (pi[k] == 3) ? r : out[3];
    }
}

// One block per id (512 blocks), 3 warps = one per feature — the session-best
// main kernel (6.40us best / 6.4-7.1 noise band): 16 front-batched LDG.128
// per warp, 31-SHFL reduce-scatter (lane l < 16 ends holding the full sum of
// d2[l>>2][l&3], replicated in the upper half-warp) + 4-SHFL gather,
// softrank on lanes 0..7, smem spearman, one atomic per block.
__global__ void __launch_bounds__(96)
cmrr_main_kernel(const float* __restrict__ f0, const float* __restrict__ f1,
                 const float* __restrict__ f2, float* __restrict__ out) {
    __shared__ float4 sh[3][8];  // [feature][row-slot] -> normalized ranks

    const int id = blockIdx.x;            // 0..511
    const int t = threadIdx.x >> 5;       // feature 0..2
    const int lane = threadIdx.x & 31;

    const int ib = id * 4;                // half-0 rows
    const int jb = 2048 + id * 4;         // half-1 rows

    const float* __restrict__ f = (t == 0) ? f0 : ((t == 1) ? f1 : f2);

    // Cooperative load: lane owns elems {lane*4..+3} and {(lane+32)*4..+3}
    float4 fa[4][2], fb[4][2];
#pragma unroll
    for (int r = 0; r < 4; r++) {
        const float4* pa =
            reinterpret_cast<const float4*>(f + (size_t)(ib + r) * 256);
        const float4* pb =
            reinterpret_cast<const float4*>(f + (size_t)(jb + r) * 256);
        fa[r][0] = pa[lane];
        fa[r][1] = pa[lane + 32];
        fb[r][0] = pb[lane];
        fb[r][1] = pb[lane + 32];
    }

    // d2 partial k = r*4+c: sum over this lane's 8 dims of (a_r - b_c)^2
    float s[16];
#pragma unroll
    for (int r = 0; r < 4; r++)
#pragma unroll
        for (int c = 0; c < 4; c++)
            s[r * 4 + c] = sd8(fa[r][0], fa[r][1], fb[c][0], fb[c][1]);

    // Stage 1: combine the two 16-lane halves (butterfly; both sides add).
#pragma unroll
    for (int k = 0; k < 16; k++)
        s[k] += __shfl_xor_sync(FULLMASK, s[k], 16);

    // Stages 2-5: reduce-scatter within each 16-lane half. After them,
    // lane l holds the full sum of value (l & 15); upper half replicates.
    float myd2;
    {
        const bool up8 = (lane & 8) != 0;
        float t8[8];
#pragma unroll
        for (int k = 0; k < 8; k++) {
            float keep = up8 ? s[k + 8] : s[k];
            float snd = up8 ? s[k] : s[k + 8];
            t8[k] = keep + __shfl_xor_sync(FULLMASK, snd, 8);
        }
        const bool up4 = (lane & 4) != 0;
        float t4[4];
#pragma unroll
        for (int k = 0; k < 4; k++) {
            float keep = up4 ? t8[k + 4] : t8[k];
            float snd = up4 ? t8[k] : t8[k + 4];
            t4[k] = keep + __shfl_xor_sync(FULLMASK, snd, 4);
        }
        const bool up2 = (lane & 2) != 0;
        float t2[2];
#pragma unroll
        for (int k = 0; k < 2; k++) {
            float keep = up2 ? t4[k + 2] : t4[k];
            float snd = up2 ? t4[k] : t4[k + 2];
            t2[k] = keep + __shfl_xor_sync(FULLMASK, snd, 2);
        }
        const bool up1 = (lane & 1) != 0;
        float keep = up1 ? t2[1] : t2[0];
        float snd = up1 ? t2[0] : t2[1];
        myd2 = keep + __shfl_xor_sync(FULLMASK, snd, 1);
    }

    // lane l (l mod 16 = r*4+c) -> distance for pair (r, c)
    float dist = sqrtf(fmaxf(myd2, 1e-12f));

    // lanes 0..3: query row ib+l,   v[c] = dist(l, c)   (src = l*4+c)
    // lanes 4..7: query row jb+(l-4), v[c] = dist(c, l-4) (src = c*4+(l-4))
    const int rr = lane & 3;
    const bool trans = (lane & 4) != 0;
    float v[4];
#pragma unroll
    for (int c = 0; c < 4; c++) {
        int src = trans ? (c * 4 + rr) : (rr * 4 + c);
        v[c] = __shfl_sync(FULLMASK, dist, src);
    }

    float rk[4];
    softrank4(v, rk);

    // center + normalize
    {
        float m = 0.25f * (rk[0] + rk[1] + rk[2] + rk[3]);
        float n2 = 0.0f;
#pragma unroll
        for (int c = 0; c < 4; c++) {
            rk[c] -= m;
            n2 = fmaf(rk[c], rk[c], n2);
        }
        float inv = rsqrtf(n2);
#pragma unroll
        for (int c = 0; c < 4; c++) rk[c] *= inv;
    }

    if (lane < 8) sh[t][lane] = make_float4(rk[0], rk[1], rk[2], rk[3]);
    __syncthreads();

    // warp 0: spearman across feature pairs for the 8 query rows, reduce,
    // accumulate the global mean.
    if (t == 0) {
        float loss = 0.0f;
        if (lane < 8) {
            float4 r0 = sh[0][lane];
            float4 r1 = sh[1][lane];
            float4 r2 = sh[2][lane];
            float sp = r0.x * r1.x + r0.y * r1.y + r0.z * r1.z + r0.w * r1.w;
            sp += r0.x * r2.x + r0.y * r2.y + r0.z * r2.z + r0.w * r2.w;
            sp += r1.x * r2.x + r1.y * r2.y + r1.z * r2.z + r1.w * r2.w;
            loss = (sp + 3.0f) * (1.0f / 6.0f);
        }
        loss += __shfl_xor_sync(FULLMASK, loss, 1);
        loss += __shfl_xor_sync(FULLMASK, loss, 2);
        loss += __shfl_xor_sync(FULLMASK, loss, 4);
        if (lane == 0) atomicAdd(out, loss * (1.0f / 4096.0f));
    }
}

extern "C" void kernel_launch(void* const* d_in, const int* in_sizes, int n_in,
                              void* d_out, int out_size) {
    const float* f0 = (const float*)d_in[0];
    const float* f1 = (const float*)d_in[1];
    const float* f2 = (const float*)d_in[2];
    float* out = (float*)d_out;

    // Zero the accumulator via an async memset node (cheaper than a kernel
    // launch; graph-capturable, allocation-free). Hard data dependency of
    // the atomics — not elidable: d_out is poisoned once before the timed
    // loop, so each replay must self-zero for replay determinism.
    cudaMemsetAsync(out, 0, sizeof(float), 0);
    cmrr_main_kernel<<<512, 96>>>(f0, f1, f2, out);
}

// round 17
// speedup vs baseline: 1.0702x; 1.0702x over previous
#include <cuda_runtime.h>

#define FULLMASK 0xFFFFFFFFu

// Sum of squared differences of two 8-float (2x float4) chunks.
__device__ __forceinline__ float sd8(const float4& a0, const float4& a1,
                                     const float4& b0, const float4& b1) {
    float t, s;
    t = a0.x - b0.x; s = t * t;
    t = a0.y - b0.y; s = fmaf(t, t, s);
    t = a0.z - b0.z; s = fmaf(t, t, s);
    t = a0.w - b0.w; s = fmaf(t, t, s);
    t = a1.x - b1.x; s = fmaf(t, t, s);
    t = a1.y - b1.y; s = fmaf(t, t, s);
    t = a1.z - b1.z; s = fmaf(t, t, s);
    t = a1.w - b1.w; s = fmaf(t, t, s);
    return s;
}

// soft_rank with KL regularization, strength 2.0, n = 4 (register-resident).
__device__ __forceinline__ void softrank4(const float v[4], float out[4]) {
    float th[4];
    int pi[4];
#pragma unroll
    for (int m = 0; m < 4; m++) { th[m] = v[m] * 0.5f; pi[m] = m; }

    // descending sort network on 4 elems: (0,1)(2,3)(0,2)(1,3)(1,2)
#define CSWAP(a, b)                                     \
    do {                                                \
        if (th[a] < th[b]) {                            \
            float tf = th[a]; th[a] = th[b]; th[b] = tf;\
            int ti = pi[a]; pi[a] = pi[b]; pi[b] = ti;  \
        }                                               \
    } while (0)
    CSWAP(0, 1); CSWAP(2, 3); CSWAP(0, 2); CSWAP(1, 3); CSWAP(1, 2);
#undef CSWAP

    const float lcw00 = 1.3862943611198906f;  // log 4
    const float lcw01 = 1.9459101090932196f;  // log 7
    const float lcw02 = 2.1972245773362196f;  // log 9
    const float lcw03 = 2.302585092994046f;   // log 10
    const float lcw11 = 1.0986122886681098f;  // log 3
    const float lcw12 = 1.6094379124341003f;  // log 5
    const float lcw13 = 1.791759469228055f;   // log 6
    const float lcw22 = 0.6931471805599453f;  // log 2
    const float lcw23 = 1.0986122886681098f;  // log 3
    const float lcw33 = 0.0f;                 // log 1

    // B[i][j] = LSE(th[i..j]) - log(cw[i][j]); th descending so th[i] is seg max.
    float B[4][4];
    {
        float run;
        run = 1.0f;                       B[0][0] = th[0] - lcw00;
        run += __expf(th[1] - th[0]);     B[0][1] = th[0] + __logf(run) - lcw01;
        run += __expf(th[2] - th[0]);     B[0][2] = th[0] + __logf(run) - lcw02;
        run += __expf(th[3] - th[0]);     B[0][3] = th[0] + __logf(run) - lcw03;
        run = 1.0f;                       B[1][1] = th[1] - lcw11;
        run += __expf(th[2] - th[1]);     B[1][2] = th[1] + __logf(run) - lcw12;
        run += __expf(th[3] - th[1]);     B[1][3] = th[1] + __logf(run) - lcw13;
        run = 1.0f;                       B[2][2] = th[2] - lcw22;
        run += __expf(th[3] - th[2]);     B[2][3] = th[2] + __logf(run) - lcw23;
        B[3][3] = th[3] - lcw33;
    }

    // dual[k] = min_{i<=k} max_{j>=k} B[i][j]
    float dual[4];
    {
        float T0_3 = B[0][3], T0_2 = fmaxf(B[0][2], T0_3),
              T0_1 = fmaxf(B[0][1], T0_2), T0_0 = fmaxf(B[0][0], T0_1);
        float T1_3 = B[1][3], T1_2 = fmaxf(B[1][2], T1_3),
              T1_1 = fmaxf(B[1][1], T1_2);
        float T2_3 = B[2][3], T2_2 = fmaxf(B[2][2], T2_3);
        float T3_3 = B[3][3];
        dual[0] = T0_0;
        dual[1] = fminf(T0_1, T1_1);
        dual[2] = fminf(fminf(T0_2, T1_2), T2_2);
        dual[3] = fminf(fminf(T0_3, T1_3), fminf(T2_3, T3_3));
    }

#pragma unroll
    for (int k = 0; k < 4; k++) {
        float r = __expf(th[k] - dual[k]);
        out[0] = (pi[k] == 0) ? r : out[0];
        out[1] = (pi[k] == 1) ? r : out[1];
        out[2] = (pi[k] == 2) ? r : out[2];
        out[3] = (pi[k] == 3) ? r : out[3];
    }
}

// One block per id (512 blocks), 3 warps = one per feature — the session-best
// main kernel (6.40us best / 6.4-7.1 noise band): 16 front-batched LDG.128
// per warp, 31-SHFL reduce-scatter (lane l < 16 ends holding the full sum of
// d2[l>>2][l&3], replicated in the upper half-warp) + 4-SHFL gather,
// softrank on lanes 0..7, smem spearman, one atomic per block.
__global__ void __launch_bounds__(96)
cmrr_main_kernel(const float* __restrict__ f0, const float* __restrict__ f1,
                 const float* __restrict__ f2, float* __restrict__ out) {
    __shared__ float4 sh[3][8];  // [feature][row-slot] -> normalized ranks

    const int id = blockIdx.x;            // 0..511
    const int t = threadIdx.x >> 5;       // feature 0..2
    const int lane = threadIdx.x & 31;

    const int ib = id * 4;                // half-0 rows
    const int jb = 2048 + id * 4;         // half-1 rows

    const float* __restrict__ f = (t == 0) ? f0 : ((t == 1) ? f1 : f2);

    // Cooperative load: lane owns elems {lane*4..+3} and {(lane+32)*4..+3}
    float4 fa[4][2], fb[4][2];
#pragma unroll
    for (int r = 0; r < 4; r++) {
        const float4* pa =
            reinterpret_cast<const float4*>(f + (size_t)(ib + r) * 256);
        const float4* pb =
            reinterpret_cast<const float4*>(f + (size_t)(jb + r) * 256);
        fa[r][0] = pa[lane];
        fa[r][1] = pa[lane + 32];
        fb[r][0] = pb[lane];
        fb[r][1] = pb[lane + 32];
    }

    // d2 partial k = r*4+c: sum over this lane's 8 dims of (a_r - b_c)^2
    float s[16];
#pragma unroll
    for (int r = 0; r < 4; r++)
#pragma unroll
        for (int c = 0; c < 4; c++)
            s[r * 4 + c] = sd8(fa[r][0], fa[r][1], fb[c][0], fb[c][1]);

    // Stage 1: combine the two 16-lane halves (butterfly; both sides add).
#pragma unroll
    for (int k = 0; k < 16; k++)
        s[k] += __shfl_xor_sync(FULLMASK, s[k], 16);

    // Stages 2-5: reduce-scatter within each 16-lane half. After them,
    // lane l holds the full sum of value (l & 15); upper half replicates.
    float myd2;
    {
        const bool up8 = (lane & 8) != 0;
        float t8[8];
#pragma unroll
        for (int k = 0; k < 8; k++) {
            float keep = up8 ? s[k + 8] : s[k];
            float snd = up8 ? s[k] : s[k + 8];
            t8[k] = keep + __shfl_xor_sync(FULLMASK, snd, 8);
        }
        const bool up4 = (lane & 4) != 0;
        float t4[4];
#pragma unroll
        for (int k = 0; k < 4; k++) {
            float keep = up4 ? t8[k + 4] : t8[k];
            float snd = up4 ? t8[k] : t8[k + 4];
            t4[k] = keep + __shfl_xor_sync(FULLMASK, snd, 4);
        }
        const bool up2 = (lane & 2) != 0;
        float t2[2];
#pragma unroll
        for (int k = 0; k < 2; k++) {
            float keep = up2 ? t4[k + 2] : t4[k];
            float snd = up2 ? t4[k] : t4[k + 2];
            t2[k] = keep + __shfl_xor_sync(FULLMASK, snd, 2);
        }
        const bool up1 = (lane & 1) != 0;
        float keep = up1 ? t2[1] : t2[0];
        float snd = up1 ? t2[0] : t2[1];
        myd2 = keep + __shfl_xor_sync(FULLMASK, snd, 1);
    }

    // lane l (l mod 16 = r*4+c) -> distance for pair (r, c)
    float dist = sqrtf(fmaxf(myd2, 1e-12f));

    // lanes 0..3: query row ib+l,   v[c] = dist(l, c)   (src = l*4+c)
    // lanes 4..7: query row jb+(l-4), v[c] = dist(c, l-4) (src = c*4+(l-4))
    const int rr = lane & 3;
    const bool trans = (lane & 4) != 0;
    float v[4];
#pragma unroll
    for (int c = 0; c < 4; c++) {
        int src = trans ? (c * 4 + rr) : (rr * 4 + c);
        v[c] = __shfl_sync(FULLMASK, dist, src);
    }

    float rk[4];
    softrank4(v, rk);

    // center + normalize
    {
        float m = 0.25f * (rk[0] + rk[1] + rk[2] + rk[3]);
        float n2 = 0.0f;
#pragma unroll
        for (int c = 0; c < 4; c++) {
            rk[c] -= m;
            n2 = fmaf(rk[c], rk[c], n2);
        }
        float inv = rsqrtf(n2);
#pragma unroll
        for (int c = 0; c < 4; c++) rk[c] *= inv;
    }

    if (lane < 8) sh[t][lane] = make_float4(rk[0], rk[1], rk[2], rk[3]);
    __syncthreads();

    // warp 0: spearman across feature pairs for the 8 query rows, reduce,
    // accumulate the global mean.
    if (t == 0) {
        float loss = 0.0f;
        if (lane < 8) {
            float4 r0 = sh[0][lane];
            float4 r1 = sh[1][lane];
            float4 r2 = sh[2][lane];
            float sp = r0.x * r1.x + r0.y * r1.y + r0.z * r1.z + r0.w * r1.w;
            sp += r0.x * r2.x + r0.y * r2.y + r0.z * r2.z + r0.w * r2.w;
            sp += r1.x * r2.x + r1.y * r2.y + r1.z * r2.z + r1.w * r2.w;
            loss = (sp + 3.0f) * (1.0f / 6.0f);
        }
        loss += __shfl_xor_sync(FULLMASK, loss, 1);
        loss += __shfl_xor_sync(FULLMASK, loss, 2);
        loss += __shfl_xor_sync(FULLMASK, loss, 4);
        if (lane == 0) atomicAdd(out, loss * (1.0f / 4096.0f));
    }
}

extern "C" void kernel_launch(void* const* d_in, const int* in_sizes, int n_in,
                              void* d_out, int out_size) {
    const float* f0 = (const float*)d_in[0];
    const float* f1 = (const float*)d_in[1];
    const float* f2 = (const float*)d_in[2];
    float* out = (float*)d_out;

    // Zero the accumulator via an async memset node (cheaper than a kernel
    // launch; graph-capturable, allocation-free). Hard data dependency of
    // the atomics — not elidable: d_out is poisoned once before the timed
    // loop, so each replay must self-zero for replay determinism.
    cudaMemsetAsync(out, 0, sizeof(float), 0);
    cmrr_main_kernel<<<512, 96>>>(f0, f1, f2, out);
}